// round 9
// baseline (speedup 1.0000x reference)
#include <cuda_runtime.h>
#include <cstdint>
#include <math.h>

// Problem constants
#define BATCH 2
#define DMODEL 1024
#define SEQ 2048
#define HEADS 16
#define HDIM 64

// Scratch (allocation-free rule: __device__ globals)
__device__ float g_Q[BATCH * DMODEL * SEQ];
__device__ float g_K[BATCH * DMODEL * SEQ];
__device__ float g_V[BATCH * DMODEL * SEQ];
__device__ float g_X[BATCH * DMODEL * SEQ];

// ===========================================================================
// Helpers
// ===========================================================================
__device__ __forceinline__ uint32_t cvt_tf32(float v) {
    uint32_t r;
    asm("cvt.rna.tf32.f32 %0, %1;" : "=r"(r) : "f"(v));
    return r;
}

// D += A * B  (m16n8k8, tf32 inputs, fp32 accum). A row-major, B "col" (n x k).
__device__ __forceinline__ void mma_tf32(float d[4], const uint32_t a[4],
                                         uint32_t b0, uint32_t b1) {
    asm volatile(
        "mma.sync.aligned.m16n8k8.row.col.f32.tf32.tf32.f32 "
        "{%0,%1,%2,%3}, {%4,%5,%6,%7}, {%8,%9}, {%0,%1,%2,%3};\n"
        : "+f"(d[0]), "+f"(d[1]), "+f"(d[2]), "+f"(d[3])
        : "r"(a[0]), "r"(a[1]), "r"(a[2]), "r"(a[3]), "r"(b0), "r"(b1));
}

// ===========================================================================
// GEMM v3: C[b][m][n] = sum_k A[m][k] * X[b][k][n] + bias[m]
// Block 128x128, 4 warps (64x64 each). K staged in chunks of 16, double-
// buffered in two static smem arrays (unroll-by-2), 1 barrier per stage.
// Fragment-major smem chunks (128 words = 512B): lane l reads uint4 at
// word (l^((l>>3)&3))*4 giving its 4 mma fragment words.
//   A chunk (mtg, ks): word (mq,kk): lp=(mq&7)*4+(kk&3),
//     slot=(mq>>3)+2*(kk>>2) -> a0..a3 for m=16*mtg+r(+8), k=8*ks+c(+4)
//   B chunk (ntp, ks): word (nn,kk): lp=(nn&7)*4+(kk&3),
//     slot=(nn>>3)*2+(kk>>2) -> b0,b1 of nt=2*ntp and 2*ntp+1
// Staging thread maps chosen so the scatter STS are bank-conflict-free.
// ===========================================================================
__device__ __forceinline__ void gemm_stage(
    const float* __restrict__ A, const float* __restrict__ Xb,
    uint32_t* __restrict__ buf, int row0, int col0, int k0, int tid)
{
    // ---- A tile: 128 m x 16 k ----
#pragma unroll
    for (int iter = 0; iter < 4; ++iter) {
        int j = (tid >> 1) & 15;                       // m low 4 bits
        int mtg = (tid >> 5) + (iter & 1) * 4;         // m group 0..7
        int m = mtg * 16 + j;
        int kloc = (iter >> 1) * 8 + (tid & 1) * 4;    // 0,4,8,12
        float4 v = *(const float4*)(A + (size_t)(row0 + m) * DMODEL + k0 + kloc);
        float vv[4] = {v.x, v.y, v.z, v.w};
        int slot = (j >> 3) + 2 * (tid & 1);
        int chunk = mtg * 2 + (iter >> 1);
#pragma unroll
        for (int e = 0; e < 4; ++e) {
            int lp = (j & 7) * 4 + e;
            int ls = lp ^ ((lp >> 3) & 3);
            buf[chunk * 128 + ls * 4 + slot] = cvt_tf32(vv[e]);
        }
    }
    // ---- B tile: 16 k x 128 n (transposed into n-major frags) ----
    {
        int kl = ((tid >> 3) & 3) + ((tid >> 2) & 1) * 4 + ((tid >> 5) & 1) * 8;
        int ks = kl >> 3;
        int kk3 = kl & 3;
        int kk2 = (kl >> 2) & 1;
        const float* src = Xb + (size_t)(k0 + kl) * SEQ + col0;
#pragma unroll
        for (int iter = 0; iter < 4; ++iter) {
            int n4 = (tid & 3) * 4 + iter * 16 + (tid >> 6) * 64;
            float4 v = *(const float4*)(src + n4);
            float vv[4] = {v.x, v.y, v.z, v.w};
#pragma unroll
            for (int e = 0; e < 4; ++e) {
                int n = n4 + e;
                int ntp = n >> 4;
                int nn = n & 15;
                int lp = (nn & 7) * 4 + kk3;
                int ls = lp ^ ((lp >> 3) & 3);
                int slot = (nn >> 3) * 2 + kk2;
                buf[2048 + (ntp * 2 + ks) * 128 + ls * 4 + slot] = cvt_tf32(vv[e]);
            }
        }
    }
}

__device__ __forceinline__ void gemm_compute(
    const uint32_t* __restrict__ buf, float acc[4][8][4],
    int wr, int wc, int lsw)
{
#pragma unroll
    for (int ks = 0; ks < 2; ++ks) {
        uint4 af[4], bf[4];
#pragma unroll
        for (int mt = 0; mt < 4; ++mt)
            af[mt] = *(const uint4*)&buf[((wr * 4 + mt) * 2 + ks) * 128 + lsw * 4];
#pragma unroll
        for (int np = 0; np < 4; ++np)
            bf[np] = *(const uint4*)&buf[2048 + ((wc * 4 + np) * 2 + ks) * 128 + lsw * 4];
#pragma unroll
        for (int mt = 0; mt < 4; ++mt) {
            uint32_t a[4] = {af[mt].x, af[mt].y, af[mt].z, af[mt].w};
#pragma unroll
            for (int np = 0; np < 4; ++np) {
                mma_tf32(acc[mt][2 * np],     a, bf[np].x, bf[np].y);
                mma_tf32(acc[mt][2 * np + 1], a, bf[np].z, bf[np].w);
            }
        }
    }
}

__global__ __launch_bounds__(128, 2) void gemm_mma3(
    const float* __restrict__ A, const float* __restrict__ X,
    const float* __restrict__ bias, float* __restrict__ C)
{
    __shared__ uint32_t sb0[4096];
    __shared__ uint32_t sb1[4096];

    const int tid = threadIdx.x;
    const int lane = tid & 31, wid = tid >> 5;
    const int wr = wid >> 1, wc = wid & 1;
    const int r = lane >> 2, c = lane & 3;
    const int lsw = lane ^ ((lane >> 3) & 3);
    const int b = blockIdx.z;
    const int row0 = blockIdx.y * 128, col0 = blockIdx.x * 128;
    const float* Xb = X + (size_t)b * DMODEL * SEQ;
    float* Cb = C + (size_t)b * DMODEL * SEQ;

    float acc[4][8][4];
#pragma unroll
    for (int mt = 0; mt < 4; ++mt)
#pragma unroll
        for (int nt = 0; nt < 8; ++nt)
#pragma unroll
            for (int i = 0; i < 4; ++i) acc[mt][nt][i] = 0.f;

    gemm_stage(A, Xb, sb0, row0, col0, 0, tid);
    __syncthreads();

#pragma unroll 1
    for (int st = 0; st < 64; st += 2) {
        gemm_stage(A, Xb, sb1, row0, col0, (st + 1) * 16, tid);
        gemm_compute(sb0, acc, wr, wc, lsw);
        __syncthreads();
        if (st + 2 < 64)
            gemm_stage(A, Xb, sb0, row0, col0, (st + 2) * 16, tid);
        gemm_compute(sb1, acc, wr, wc, lsw);
        __syncthreads();
    }

    // Epilogue: fused bias, direct float2 stores
#pragma unroll
    for (int mt = 0; mt < 4; ++mt) {
        int r0 = row0 + wr * 64 + mt * 16 + r;
        float bv0 = __ldg(bias + r0);
        float bv1 = __ldg(bias + r0 + 8);
#pragma unroll
        for (int np = 0; np < 4; ++np) {
#pragma unroll
            for (int oo = 0; oo < 2; ++oo) {
                int cc = col0 + wc * 64 + np * 16 + oo * 8 + c * 2;
                const float* ac = acc[mt][2 * np + oo];
                *(float2*)(Cb + (size_t)r0 * SEQ + cc) =
                    make_float2(ac[0] + bv0, ac[1] + bv0);
                *(float2*)(Cb + (size_t)(r0 + 8) * SEQ + cc) =
                    make_float2(ac[2] + bv1, ac[3] + bv1);
            }
        }
    }
}

// ===========================================================================
// Flash attention v2 (verbatim from R8 — fragment-major, LDS.128 frags,
// 32 q/warp, pipelined LDG).
// ===========================================================================
#define QF_OFF 0
#define PF_OFF 8192
#define KF_OFF 16384
#define VF_OFF 20480
#define ATTN_SMEM_B (24576 * 4)
#define XPITCH 140

__global__ __launch_bounds__(128, 2) void attn_mma2(
    const float* __restrict__ Q, const float* __restrict__ K,
    const float* __restrict__ V, float* __restrict__ O)
{
    extern __shared__ uint32_t sm[];

    const int tid = threadIdx.x;
    const int lane = tid & 31, wid = tid >> 5;
    const int r = lane >> 2, c = lane & 3;
    const int lsw = lane ^ ((lane >> 3) & 3);

    const int bh = blockIdx.y;
    const int b = bh >> 4, h = bh & 15;
    const int n0 = blockIdx.x * 128;
    const size_t base = (size_t)b * DMODEL * SEQ + (size_t)h * SEQ;
    const size_t ds = (size_t)HEADS * SEQ;

    // ---------------- Stage Q (fragment-major, scaled, tf32) ----------------
    {
        const int qd0 = tid >> 5;
        const int qq0 = (lane) * 4;
#pragma unroll
        for (int it = 0; it < 16; ++it) {
            int d = qd0 + it * 4;
            float4 v = *(const float4*)(Q + base + (size_t)d * ds + n0 + qq0);
            float vv[4] = {v.x, v.y, v.z, v.w};
            int ks = d >> 3, cc = d & 3, ch = (d >> 2) & 1;
#pragma unroll
            for (int e = 0; e < 4; ++e) {
                int qq = qq0 + e;
                int wq = qq >> 5, qr = qq & 31, mt = qr >> 4, rr = qr & 15;
                int rw = rr & 7, rh = rr >> 3;
                int lp = rw * 4 + cc;
                int ls = lp ^ ((lp >> 3) & 3);
                sm[QF_OFF + wq * 2048 + (mt * 8 + ks) * 128 + ls * 4 + rh + 2 * ch]
                    = cvt_tf32(vv[e] * 0.125f);
            }
        }
    }

    const int sj0 = (tid & 15) * 4;
    const int sd0 = tid >> 4;
    const float* kbase = K + base + (size_t)sd0 * ds + sj0;
    const float* vbase = V + base + (size_t)sd0 * ds + sj0;

    const int k_cc = sd0 & 3, k_hi = (sd0 >> 2) & 1;
    const int k_nt = (tid & 15) >> 1;
    const int v_ks = (tid & 15) >> 1;
    const int v_r = sd0, v_hi = tid & 1;

    float m_[2][2] = {{-1e30f, -1e30f}, {-1e30f, -1e30f}};
    float l_[2][2] = {{0.f, 0.f}, {0.f, 0.f}};
    float acc[2][8][4];
#pragma unroll
    for (int mt = 0; mt < 2; ++mt)
#pragma unroll
        for (int nt = 0; nt < 8; ++nt)
#pragma unroll
            for (int i = 0; i < 4; ++i) acc[mt][nt][i] = 0.f;

    float4 kreg[8], vreg[8];

#pragma unroll
    for (int it = 0; it < 8; ++it) {
        kreg[it] = *(const float4*)(kbase + (size_t)it * 8 * ds);
        vreg[it] = *(const float4*)(vbase + (size_t)it * 8 * ds);
    }
#pragma unroll
    for (int it = 0; it < 8; ++it) {
        float kv[4] = {kreg[it].x, kreg[it].y, kreg[it].z, kreg[it].w};
        float vv[4] = {vreg[it].x, vreg[it].y, vreg[it].z, vreg[it].w};
#pragma unroll
        for (int e = 0; e < 4; ++e) {
            int rs = 4 * (tid & 1) + e;
            int lpk = rs * 4 + k_cc;
            int lsk = lpk ^ ((lpk >> 3) & 3);
            sm[KF_OFF + (it * 4 + (k_nt >> 1)) * 128 + lsk * 4
               + (k_nt & 1) * 2 + k_hi] = cvt_tf32(kv[e]);
            int lpv = v_r * 4 + e;
            int lsv = lpv ^ ((lpv >> 3) & 3);
            sm[VF_OFF + (v_ks * 4 + (it >> 1)) * 128 + lsv * 4
               + (it & 1) * 2 + v_hi] = cvt_tf32(vv[e]);
        }
    }
    __syncthreads();

    const int lp0 = r * 4 + ((2 * c) & 3);
    const int ls0 = lp0 ^ ((lp0 >> 3) & 3);
    const int lp1 = r * 4 + ((2 * c + 1) & 3);
    const int ls1 = lp1 ^ ((lp1 >> 3) & 3);
    const int pch = (c >= 2) ? 2 : 0;
    const int PW = PF_OFF + wid * 2048;
    const int QW_ = QF_OFF + wid * 2048;

    for (int t = 0; t < SEQ; t += 64) {
        const bool more = (t + 64) < SEQ;
        if (more) {
#pragma unroll
            for (int it = 0; it < 8; ++it)
                kreg[it] = *(const float4*)(kbase + (size_t)it * 8 * ds + t + 64);
        }

        float s[2][8][4];
#pragma unroll
        for (int mt = 0; mt < 2; ++mt)
#pragma unroll
            for (int nt = 0; nt < 8; ++nt)
#pragma unroll
                for (int i = 0; i < 4; ++i) s[mt][nt][i] = 0.f;

#pragma unroll
        for (int ks = 0; ks < 8; ++ks) {
            uint4 qa0 = *(const uint4*)&sm[QW_ + ks * 128 + lsw * 4];
            uint4 qa1 = *(const uint4*)&sm[QW_ + (8 + ks) * 128 + lsw * 4];
            uint32_t a0[4] = {qa0.x, qa0.y, qa0.z, qa0.w};
            uint32_t a1[4] = {qa1.x, qa1.y, qa1.z, qa1.w};
#pragma unroll
            for (int ntp = 0; ntp < 4; ++ntp) {
                uint4 kf = *(const uint4*)&sm[KF_OFF + (ks * 4 + ntp) * 128 + lsw * 4];
                mma_tf32(s[0][2 * ntp], a0, kf.x, kf.y);
                mma_tf32(s[0][2 * ntp + 1], a0, kf.z, kf.w);
                mma_tf32(s[1][2 * ntp], a1, kf.x, kf.y);
                mma_tf32(s[1][2 * ntp + 1], a1, kf.z, kf.w);
            }
        }

        __syncthreads();
        if (more) {
#pragma unroll
            for (int it = 0; it < 8; ++it) {
                float kv[4] = {kreg[it].x, kreg[it].y, kreg[it].z, kreg[it].w};
#pragma unroll
                for (int e = 0; e < 4; ++e) {
                    int rs = 4 * (tid & 1) + e;
                    int lpk = rs * 4 + k_cc;
                    int lsk = lpk ^ ((lpk >> 3) & 3);
                    sm[KF_OFF + (it * 4 + (k_nt >> 1)) * 128 + lsk * 4
                       + (k_nt & 1) * 2 + k_hi] = cvt_tf32(kv[e]);
                }
            }
#pragma unroll
            for (int it = 0; it < 8; ++it)
                vreg[it] = *(const float4*)(vbase + (size_t)it * 8 * ds + t + 64);
        }

#pragma unroll
        for (int mt = 0; mt < 2; ++mt) {
#pragma unroll
            for (int hh = 0; hh < 2; ++hh) {
                float mx = -1e30f;
#pragma unroll
                for (int nt = 0; nt < 8; ++nt)
                    mx = fmaxf(mx, fmaxf(s[mt][nt][2 * hh], s[mt][nt][2 * hh + 1]));
                mx = fmaxf(mx, __shfl_xor_sync(0xffffffffu, mx, 1));
                mx = fmaxf(mx, __shfl_xor_sync(0xffffffffu, mx, 2));
                float mn = fmaxf(m_[mt][hh], mx);
                float sc = __expf(m_[mt][hh] - mn);
                float sum = 0.f;
#pragma unroll
                for (int nt = 0; nt < 8; ++nt) {
                    float e0 = __expf(s[mt][nt][2 * hh] - mn);
                    float e1 = __expf(s[mt][nt][2 * hh + 1] - mn);
                    s[mt][nt][2 * hh] = e0;
                    s[mt][nt][2 * hh + 1] = e1;
                    sum += e0 + e1;
                }
                sum += __shfl_xor_sync(0xffffffffu, sum, 1);
                sum += __shfl_xor_sync(0xffffffffu, sum, 2);
                l_[mt][hh] = l_[mt][hh] * sc + sum;
                m_[mt][hh] = mn;
#pragma unroll
                for (int nt = 0; nt < 8; ++nt) {
                    acc[mt][nt][2 * hh] *= sc;
                    acc[mt][nt][2 * hh + 1] *= sc;
                }
            }
        }

#pragma unroll
        for (int mt = 0; mt < 2; ++mt) {
#pragma unroll
            for (int nt = 0; nt < 8; ++nt) {
                int pb = PW + (mt * 8 + nt) * 128;
                sm[pb + ls0 * 4 + 0 + pch] = cvt_tf32(s[mt][nt][0]);
                sm[pb + ls1 * 4 + 0 + pch] = cvt_tf32(s[mt][nt][1]);
                sm[pb + ls0 * 4 + 1 + pch] = cvt_tf32(s[mt][nt][2]);
                sm[pb + ls1 * 4 + 1 + pch] = cvt_tf32(s[mt][nt][3]);
            }
        }
        __syncwarp();

#pragma unroll
        for (int ks = 0; ks < 8; ++ks) {
            uint4 pa0 = *(const uint4*)&sm[PW + ks * 128 + lsw * 4];
            uint4 pa1 = *(const uint4*)&sm[PW + (8 + ks) * 128 + lsw * 4];
            uint32_t a0[4] = {pa0.x, pa0.y, pa0.z, pa0.w};
            uint32_t a1[4] = {pa1.x, pa1.y, pa1.z, pa1.w};
#pragma unroll
            for (int ntp = 0; ntp < 4; ++ntp) {
                uint4 vf = *(const uint4*)&sm[VF_OFF + (ks * 4 + ntp) * 128 + lsw * 4];
                mma_tf32(acc[0][2 * ntp], a0, vf.x, vf.y);
                mma_tf32(acc[0][2 * ntp + 1], a0, vf.z, vf.w);
                mma_tf32(acc[1][2 * ntp], a1, vf.x, vf.y);
                mma_tf32(acc[1][2 * ntp + 1], a1, vf.z, vf.w);
            }
        }

        __syncthreads();
        if (more) {
#pragma unroll
            for (int it = 0; it < 8; ++it) {
                float vv[4] = {vreg[it].x, vreg[it].y, vreg[it].z, vreg[it].w};
#pragma unroll
                for (int e = 0; e < 4; ++e) {
                    int lpv = v_r * 4 + e;
                    int lsv = lpv ^ ((lpv >> 3) & 3);
                    sm[VF_OFF + (v_ks * 4 + (it >> 1)) * 128 + lsv * 4
                       + (it & 1) * 2 + v_hi] = cvt_tf32(vv[e]);
                }
            }
        }
    }

    __syncthreads();
    float* Xs = (float*)sm;
#pragma unroll
    for (int mt = 0; mt < 2; ++mt) {
#pragma unroll
        for (int hh = 0; hh < 2; ++hh) {
            float inv = 1.f / l_[mt][hh];
            int q = wid * 32 + mt * 16 + r + 8 * hh;
#pragma unroll
            for (int nt = 0; nt < 8; ++nt) {
                int d0 = nt * 8 + 2 * c;
                Xs[d0 * XPITCH + q] = acc[mt][nt][2 * hh] * inv;
                Xs[(d0 + 1) * XPITCH + q] = acc[mt][nt][2 * hh + 1] * inv;
            }
        }
    }
    __syncthreads();
#pragma unroll
    for (int it = 0; it < 16; ++it) {
        int d = (tid >> 5) + it * 4;
        float4 v = *(const float4*)&Xs[d * XPITCH + lane * 4];
        *(float4*)(O + base + (size_t)d * ds + n0 + lane * 4) = v;
    }
}

// ---------------------------------------------------------------------------
// Launch.  metadata order: query, key, value, Wq, bq, Wk, bk, Wv, bv, Wm, bm
// ---------------------------------------------------------------------------
extern "C" void kernel_launch(void* const* d_in, const int* in_sizes, int n_in,
                              void* d_out, int out_size)
{
    const float* query = (const float*)d_in[0];
    const float* key   = (const float*)d_in[1];
    const float* value = (const float*)d_in[2];
    const float* Wq = (const float*)d_in[3];
    const float* bq = (const float*)d_in[4];
    const float* Wk = (const float*)d_in[5];
    const float* bk = (const float*)d_in[6];
    const float* Wv = (const float*)d_in[7];
    const float* bv = (const float*)d_in[8];
    const float* Wm = (const float*)d_in[9];
    const float* bm = (const float*)d_in[10];
    float* out = (float*)d_out;

    float *Qp, *Kp, *Vp, *Xp;
    cudaGetSymbolAddress((void**)&Qp, g_Q);
    cudaGetSymbolAddress((void**)&Kp, g_K);
    cudaGetSymbolAddress((void**)&Vp, g_V);
    cudaGetSymbolAddress((void**)&Xp, g_X);

    cudaFuncSetAttribute(attn_mma2,
                         cudaFuncAttributeMaxDynamicSharedMemorySize,
                         ATTN_SMEM_B);

    dim3 gGemm(SEQ / 128, DMODEL / 128, BATCH);  // (16, 8, 2)
    dim3 bGemm(128);

    gemm_mma3<<<gGemm, bGemm>>>(Wq, query, bq, Qp);
    gemm_mma3<<<gGemm, bGemm>>>(Wk, key,   bk, Kp);
    gemm_mma3<<<gGemm, bGemm>>>(Wv, value, bv, Vp);

    dim3 gAttn(SEQ / 128, BATCH * HEADS);  // (16, 32)
    attn_mma2<<<gAttn, 128, ATTN_SMEM_B>>>(Qp, Kp, Vp, Xp);

    gemm_mma3<<<gGemm, bGemm>>>(Wm, Xp, bm, out);
}

// round 13
// speedup vs baseline: 1.1562x; 1.1562x over previous
#include <cuda_runtime.h>
#include <cstdint>
#include <math.h>

// Problem constants
#define BATCH 2
#define DMODEL 1024
#define SEQ 2048
#define HEADS 16
#define HDIM 64

// Scratch (allocation-free rule: __device__ globals)
__device__ float g_Q[BATCH * DMODEL * SEQ];
__device__ float g_K[BATCH * DMODEL * SEQ];
__device__ float g_V[BATCH * DMODEL * SEQ];
__device__ float g_X[BATCH * DMODEL * SEQ];

// ===========================================================================
// Helpers
// ===========================================================================
__device__ __forceinline__ uint32_t cvt_tf32(float v) {
    uint32_t r;
    asm("cvt.rna.tf32.f32 %0, %1;" : "=r"(r) : "f"(v));
    return r;
}

// D += A * B  (m16n8k8, tf32 inputs, fp32 accum). A row-major, B "col" (n x k).
__device__ __forceinline__ void mma_tf32(float d[4], const uint32_t a[4],
                                         uint32_t b0, uint32_t b1) {
    asm volatile(
        "mma.sync.aligned.m16n8k8.row.col.f32.tf32.tf32.f32 "
        "{%0,%1,%2,%3}, {%4,%5,%6,%7}, {%8,%9}, {%0,%1,%2,%3};\n"
        : "+f"(d[0]), "+f"(d[1]), "+f"(d[2]), "+f"(d[3])
        : "r"(a[0]), "r"(a[1]), "r"(a[2]), "r"(a[3]), "r"(b0), "r"(b1));
}

// ===========================================================================
// GEMM with bias (tensor-core tf32) — R8 version verbatim (proven fastest)
// ===========================================================================
#define APITCH 36
#define BPITCH 136

__global__ __launch_bounds__(256, 2) void gemm_mma(
    const float* __restrict__ A, const float* __restrict__ X,
    const float* __restrict__ bias, float* __restrict__ C)
{
    __shared__ uint32_t As[128 * APITCH];
    __shared__ uint32_t Bs[32 * BPITCH];

    const int tid = threadIdx.x;
    const int lane = tid & 31;
    const int wid = tid >> 5;
    const int wm = (wid >> 2) * 64;
    const int wn = (wid & 3) * 32;
    const int r = lane >> 2, c = lane & 3;
    const int b = blockIdx.z;
    const int row0 = blockIdx.y * 128, col0 = blockIdx.x * 128;
    const float* Xb = X + (size_t)b * DMODEL * SEQ;
    float* Cb = C + (size_t)b * DMODEL * SEQ;

    float acc[4][4][4];
#pragma unroll
    for (int mt = 0; mt < 4; mt++)
#pragma unroll
        for (int nt = 0; nt < 4; nt++)
#pragma unroll
            for (int i = 0; i < 4; i++) acc[mt][nt][i] = 0.f;

    for (int kt = 0; kt < DMODEL / 32; ++kt) {
        const int k0 = kt * 32;
        __syncthreads();
#pragma unroll
        for (int it = 0; it < 4; ++it) {
            int id = tid + it * 256;
            int m = id >> 3, k4 = (id & 7) << 2;
            float4 v = *(const float4*)(A + (size_t)(row0 + m) * DMODEL + k0 + k4);
            uint4 u = make_uint4(cvt_tf32(v.x), cvt_tf32(v.y),
                                 cvt_tf32(v.z), cvt_tf32(v.w));
            *(uint4*)&As[m * APITCH + k4] = u;
        }
#pragma unroll
        for (int it = 0; it < 4; ++it) {
            int id = tid + it * 256;
            int k = id >> 5, n4 = (id & 31) << 2;
            float4 v = *(const float4*)(Xb + (size_t)(k0 + k) * SEQ + col0 + n4);
            uint4 u = make_uint4(cvt_tf32(v.x), cvt_tf32(v.y),
                                 cvt_tf32(v.z), cvt_tf32(v.w));
            *(uint4*)&Bs[k * BPITCH + n4] = u;
        }
        __syncthreads();

#pragma unroll
        for (int ks = 0; ks < 4; ++ks) {
            uint32_t af[4][4], bf[4][2];
#pragma unroll
            for (int mt = 0; mt < 4; ++mt) {
                int mr = wm + mt * 16 + r;
                af[mt][0] = As[mr * APITCH + ks * 8 + c];
                af[mt][1] = As[(mr + 8) * APITCH + ks * 8 + c];
                af[mt][2] = As[mr * APITCH + ks * 8 + c + 4];
                af[mt][3] = As[(mr + 8) * APITCH + ks * 8 + c + 4];
            }
#pragma unroll
            for (int nt = 0; nt < 4; ++nt) {
                int nc = wn + nt * 8 + r;
                bf[nt][0] = Bs[(ks * 8 + c) * BPITCH + nc];
                bf[nt][1] = Bs[(ks * 8 + c + 4) * BPITCH + nc];
            }
#pragma unroll
            for (int mt = 0; mt < 4; ++mt)
#pragma unroll
                for (int nt = 0; nt < 4; ++nt)
                    mma_tf32(acc[mt][nt], af[mt], bf[nt][0], bf[nt][1]);
        }
    }

#pragma unroll
    for (int mt = 0; mt < 4; ++mt) {
        int r0 = row0 + wm + mt * 16 + r;
        float bv0 = __ldg(bias + r0);
        float bv1 = __ldg(bias + r0 + 8);
#pragma unroll
        for (int nt = 0; nt < 4; ++nt) {
            int c0 = col0 + wn + nt * 8 + c * 2;
            float2 v0 = make_float2(acc[mt][nt][0] + bv0, acc[mt][nt][1] + bv0);
            float2 v1 = make_float2(acc[mt][nt][2] + bv1, acc[mt][nt][3] + bv1);
            *(float2*)(Cb + (size_t)r0 * SEQ + c0) = v0;
            *(float2*)(Cb + (size_t)(r0 + 8) * SEQ + c0) = v1;
        }
    }
}

// ===========================================================================
// Flash attention v2 (R8) with one change: log2e folded into Q scale,
// softmax uses exp2f (base-2 domain; mathematically identical).
// ===========================================================================
#define QF_OFF 0
#define PF_OFF 8192
#define KF_OFF 16384
#define VF_OFF 20480
#define ATTN_SMEM_B (24576 * 4)
#define XPITCH 140
#define QSCALE 0.1803368801111204f   // 0.125 * log2(e)

__global__ __launch_bounds__(128, 2) void attn_mma2(
    const float* __restrict__ Q, const float* __restrict__ K,
    const float* __restrict__ V, float* __restrict__ O)
{
    extern __shared__ uint32_t sm[];

    const int tid = threadIdx.x;
    const int lane = tid & 31, wid = tid >> 5;
    const int r = lane >> 2, c = lane & 3;
    const int lsw = lane ^ ((lane >> 3) & 3);

    const int bh = blockIdx.y;
    const int b = bh >> 4, h = bh & 15;
    const int n0 = blockIdx.x * 128;
    const size_t base = (size_t)b * DMODEL * SEQ + (size_t)h * SEQ;
    const size_t ds = (size_t)HEADS * SEQ;

    // ---------------- Stage Q (fragment-major, scaled, tf32) ----------------
    {
        const int qd0 = tid >> 5;
        const int qq0 = (lane) * 4;
#pragma unroll
        for (int it = 0; it < 16; ++it) {
            int d = qd0 + it * 4;
            float4 v = *(const float4*)(Q + base + (size_t)d * ds + n0 + qq0);
            float vv[4] = {v.x, v.y, v.z, v.w};
            int ks = d >> 3, cc = d & 3, ch = (d >> 2) & 1;
#pragma unroll
            for (int e = 0; e < 4; ++e) {
                int qq = qq0 + e;
                int wq = qq >> 5, qr = qq & 31, mt = qr >> 4, rr = qr & 15;
                int rw = rr & 7, rh = rr >> 3;
                int lp = rw * 4 + cc;
                int ls = lp ^ ((lp >> 3) & 3);
                sm[QF_OFF + wq * 2048 + (mt * 8 + ks) * 128 + ls * 4 + rh + 2 * ch]
                    = cvt_tf32(vv[e] * QSCALE);
            }
        }
    }

    const int sj0 = (tid & 15) * 4;
    const int sd0 = tid >> 4;
    const float* kbase = K + base + (size_t)sd0 * ds + sj0;
    const float* vbase = V + base + (size_t)sd0 * ds + sj0;

    const int k_cc = sd0 & 3, k_hi = (sd0 >> 2) & 1;
    const int k_nt = (tid & 15) >> 1;
    const int v_ks = (tid & 15) >> 1;
    const int v_r = sd0, v_hi = tid & 1;

    float m_[2][2] = {{-1e30f, -1e30f}, {-1e30f, -1e30f}};
    float l_[2][2] = {{0.f, 0.f}, {0.f, 0.f}};
    float acc[2][8][4];
#pragma unroll
    for (int mt = 0; mt < 2; ++mt)
#pragma unroll
        for (int nt = 0; nt < 8; ++nt)
#pragma unroll
            for (int i = 0; i < 4; ++i) acc[mt][nt][i] = 0.f;

    float4 kreg[8], vreg[8];

#pragma unroll
    for (int it = 0; it < 8; ++it) {
        kreg[it] = *(const float4*)(kbase + (size_t)it * 8 * ds);
        vreg[it] = *(const float4*)(vbase + (size_t)it * 8 * ds);
    }
#pragma unroll
    for (int it = 0; it < 8; ++it) {
        float kv[4] = {kreg[it].x, kreg[it].y, kreg[it].z, kreg[it].w};
        float vv[4] = {vreg[it].x, vreg[it].y, vreg[it].z, vreg[it].w};
#pragma unroll
        for (int e = 0; e < 4; ++e) {
            int rs = 4 * (tid & 1) + e;
            int lpk = rs * 4 + k_cc;
            int lsk = lpk ^ ((lpk >> 3) & 3);
            sm[KF_OFF + (it * 4 + (k_nt >> 1)) * 128 + lsk * 4
               + (k_nt & 1) * 2 + k_hi] = cvt_tf32(kv[e]);
            int lpv = v_r * 4 + e;
            int lsv = lpv ^ ((lpv >> 3) & 3);
            sm[VF_OFF + (v_ks * 4 + (it >> 1)) * 128 + lsv * 4
               + (it & 1) * 2 + v_hi] = cvt_tf32(vv[e]);
        }
    }
    __syncthreads();

    const int lp0 = r * 4 + ((2 * c) & 3);
    const int ls0 = lp0 ^ ((lp0 >> 3) & 3);
    const int lp1 = r * 4 + ((2 * c + 1) & 3);
    const int ls1 = lp1 ^ ((lp1 >> 3) & 3);
    const int pch = (c >= 2) ? 2 : 0;
    const int PW = PF_OFF + wid * 2048;
    const int QW_ = QF_OFF + wid * 2048;

    for (int t = 0; t < SEQ; t += 64) {
        const bool more = (t + 64) < SEQ;
        if (more) {
#pragma unroll
            for (int it = 0; it < 8; ++it)
                kreg[it] = *(const float4*)(kbase + (size_t)it * 8 * ds + t + 64);
        }

        float s[2][8][4];
#pragma unroll
        for (int mt = 0; mt < 2; ++mt)
#pragma unroll
            for (int nt = 0; nt < 8; ++nt)
#pragma unroll
                for (int i = 0; i < 4; ++i) s[mt][nt][i] = 0.f;

#pragma unroll
        for (int ks = 0; ks < 8; ++ks) {
            uint4 qa0 = *(const uint4*)&sm[QW_ + ks * 128 + lsw * 4];
            uint4 qa1 = *(const uint4*)&sm[QW_ + (8 + ks) * 128 + lsw * 4];
            uint32_t a0[4] = {qa0.x, qa0.y, qa0.z, qa0.w};
            uint32_t a1[4] = {qa1.x, qa1.y, qa1.z, qa1.w};
#pragma unroll
            for (int ntp = 0; ntp < 4; ++ntp) {
                uint4 kf = *(const uint4*)&sm[KF_OFF + (ks * 4 + ntp) * 128 + lsw * 4];
                mma_tf32(s[0][2 * ntp], a0, kf.x, kf.y);
                mma_tf32(s[0][2 * ntp + 1], a0, kf.z, kf.w);
                mma_tf32(s[1][2 * ntp], a1, kf.x, kf.y);
                mma_tf32(s[1][2 * ntp + 1], a1, kf.z, kf.w);
            }
        }

        __syncthreads();
        if (more) {
#pragma unroll
            for (int it = 0; it < 8; ++it) {
                float kv[4] = {kreg[it].x, kreg[it].y, kreg[it].z, kreg[it].w};
#pragma unroll
                for (int e = 0; e < 4; ++e) {
                    int rs = 4 * (tid & 1) + e;
                    int lpk = rs * 4 + k_cc;
                    int lsk = lpk ^ ((lpk >> 3) & 3);
                    sm[KF_OFF + (it * 4 + (k_nt >> 1)) * 128 + lsk * 4
                       + (k_nt & 1) * 2 + k_hi] = cvt_tf32(kv[e]);
                }
            }
#pragma unroll
            for (int it = 0; it < 8; ++it)
                vreg[it] = *(const float4*)(vbase + (size_t)it * 8 * ds + t + 64);
        }

#pragma unroll
        for (int mt = 0; mt < 2; ++mt) {
#pragma unroll
            for (int hh = 0; hh < 2; ++hh) {
                float mx = -1e30f;
#pragma unroll
                for (int nt = 0; nt < 8; ++nt)
                    mx = fmaxf(mx, fmaxf(s[mt][nt][2 * hh], s[mt][nt][2 * hh + 1]));
                mx = fmaxf(mx, __shfl_xor_sync(0xffffffffu, mx, 1));
                mx = fmaxf(mx, __shfl_xor_sync(0xffffffffu, mx, 2));
                float mn = fmaxf(m_[mt][hh], mx);
                float sc = exp2f(m_[mt][hh] - mn);
                float sum = 0.f;
#pragma unroll
                for (int nt = 0; nt < 8; ++nt) {
                    float e0 = exp2f(s[mt][nt][2 * hh] - mn);
                    float e1 = exp2f(s[mt][nt][2 * hh + 1] - mn);
                    s[mt][nt][2 * hh] = e0;
                    s[mt][nt][2 * hh + 1] = e1;
                    sum += e0 + e1;
                }
                sum += __shfl_xor_sync(0xffffffffu, sum, 1);
                sum += __shfl_xor_sync(0xffffffffu, sum, 2);
                l_[mt][hh] = l_[mt][hh] * sc + sum;
                m_[mt][hh] = mn;
#pragma unroll
                for (int nt = 0; nt < 8; ++nt) {
                    acc[mt][nt][2 * hh] *= sc;
                    acc[mt][nt][2 * hh + 1] *= sc;
                }
            }
        }

#pragma unroll
        for (int mt = 0; mt < 2; ++mt) {
#pragma unroll
            for (int nt = 0; nt < 8; ++nt) {
                int pb = PW + (mt * 8 + nt) * 128;
                sm[pb + ls0 * 4 + 0 + pch] = cvt_tf32(s[mt][nt][0]);
                sm[pb + ls1 * 4 + 0 + pch] = cvt_tf32(s[mt][nt][1]);
                sm[pb + ls0 * 4 + 1 + pch] = cvt_tf32(s[mt][nt][2]);
                sm[pb + ls1 * 4 + 1 + pch] = cvt_tf32(s[mt][nt][3]);
            }
        }
        __syncwarp();

#pragma unroll
        for (int ks = 0; ks < 8; ++ks) {
            uint4 pa0 = *(const uint4*)&sm[PW + ks * 128 + lsw * 4];
            uint4 pa1 = *(const uint4*)&sm[PW + (8 + ks) * 128 + lsw * 4];
            uint32_t a0[4] = {pa0.x, pa0.y, pa0.z, pa0.w};
            uint32_t a1[4] = {pa1.x, pa1.y, pa1.z, pa1.w};
#pragma unroll
            for (int ntp = 0; ntp < 4; ++ntp) {
                uint4 vf = *(const uint4*)&sm[VF_OFF + (ks * 4 + ntp) * 128 + lsw * 4];
                mma_tf32(acc[0][2 * ntp], a0, vf.x, vf.y);
                mma_tf32(acc[0][2 * ntp + 1], a0, vf.z, vf.w);
                mma_tf32(acc[1][2 * ntp], a1, vf.x, vf.y);
                mma_tf32(acc[1][2 * ntp + 1], a1, vf.z, vf.w);
            }
        }

        __syncthreads();
        if (more) {
#pragma unroll
            for (int it = 0; it < 8; ++it) {
                float vv[4] = {vreg[it].x, vreg[it].y, vreg[it].z, vreg[it].w};
#pragma unroll
                for (int e = 0; e < 4; ++e) {
                    int lpv = v_r * 4 + e;
                    int lsv = lpv ^ ((lpv >> 3) & 3);
                    sm[VF_OFF + (v_ks * 4 + (it >> 1)) * 128 + lsv * 4
                       + (it & 1) * 2 + v_hi] = cvt_tf32(vv[e]);
                }
            }
        }
    }

    __syncthreads();
    float* Xs = (float*)sm;
#pragma unroll
    for (int mt = 0; mt < 2; ++mt) {
#pragma unroll
        for (int hh = 0; hh < 2; ++hh) {
            float inv = 1.f / l_[mt][hh];
            int q = wid * 32 + mt * 16 + r + 8 * hh;
#pragma unroll
            for (int nt = 0; nt < 8; ++nt) {
                int d0 = nt * 8 + 2 * c;
                Xs[d0 * XPITCH + q] = acc[mt][nt][2 * hh] * inv;
                Xs[(d0 + 1) * XPITCH + q] = acc[mt][nt][2 * hh + 1] * inv;
            }
        }
    }
    __syncthreads();
#pragma unroll
    for (int it = 0; it < 16; ++it) {
        int d = (tid >> 5) + it * 4;
        float4 v = *(const float4*)&Xs[d * XPITCH + lane * 4];
        *(float4*)(O + base + (size_t)d * ds + n0 + lane * 4) = v;
    }
}

// ---------------------------------------------------------------------------
// Launch.  metadata order: query, key, value, Wq, bq, Wk, bk, Wv, bv, Wm, bm
// Q/K/V projections are independent -> run on 3 streams (event fork/join,
// graph-capture-safe pattern).
// ---------------------------------------------------------------------------
extern "C" void kernel_launch(void* const* d_in, const int* in_sizes, int n_in,
                              void* d_out, int out_size)
{
    const float* query = (const float*)d_in[0];
    const float* key   = (const float*)d_in[1];
    const float* value = (const float*)d_in[2];
    const float* Wq = (const float*)d_in[3];
    const float* bq = (const float*)d_in[4];
    const float* Wk = (const float*)d_in[5];
    const float* bk = (const float*)d_in[6];
    const float* Wv = (const float*)d_in[7];
    const float* bv = (const float*)d_in[8];
    const float* Wm = (const float*)d_in[9];
    const float* bm = (const float*)d_in[10];
    float* out = (float*)d_out;

    float *Qp, *Kp, *Vp, *Xp;
    cudaGetSymbolAddress((void**)&Qp, g_Q);
    cudaGetSymbolAddress((void**)&Kp, g_K);
    cudaGetSymbolAddress((void**)&Vp, g_V);
    cudaGetSymbolAddress((void**)&Xp, g_X);

    static cudaStream_t s1, s2;
    static cudaEvent_t evRoot, ev1, ev2;
    static bool init_done = false;
    if (!init_done) {
        cudaFuncSetAttribute(attn_mma2,
                             cudaFuncAttributeMaxDynamicSharedMemorySize,
                             ATTN_SMEM_B);
        cudaStreamCreateWithFlags(&s1, cudaStreamNonBlocking);
        cudaStreamCreateWithFlags(&s2, cudaStreamNonBlocking);
        cudaEventCreateWithFlags(&evRoot, cudaEventDisableTiming);
        cudaEventCreateWithFlags(&ev1, cudaEventDisableTiming);
        cudaEventCreateWithFlags(&ev2, cudaEventDisableTiming);
        init_done = true;
    }

    dim3 gGemm(SEQ / 128, DMODEL / 128, BATCH);  // (16, 8, 2)
    dim3 bGemm(256);

    // Fork: side streams join the capture via the root event.
    cudaEventRecord(evRoot, 0);
    cudaStreamWaitEvent(s1, evRoot, 0);
    cudaStreamWaitEvent(s2, evRoot, 0);

    gemm_mma<<<gGemm, bGemm, 0, 0>>>(Wq, query, bq, Qp);
    gemm_mma<<<gGemm, bGemm, 0, s1>>>(Wk, key,   bk, Kp);
    gemm_mma<<<gGemm, bGemm, 0, s2>>>(Wv, value, bv, Vp);

    // Join back onto the main stream.
    cudaEventRecord(ev1, s1);
    cudaEventRecord(ev2, s2);
    cudaStreamWaitEvent(0, ev1, 0);
    cudaStreamWaitEvent(0, ev2, 0);

    dim3 gAttn(SEQ / 128, BATCH * HEADS);  // (16, 32)
    attn_mma2<<<gAttn, 128, ATTN_SMEM_B>>>(Qp, Kp, Vp, Xp);

    gemm_mma<<<gGemm, bGemm>>>(Wm, Xp, bm, out);
}

// round 14
// speedup vs baseline: 1.5709x; 1.3587x over previous
#include <cuda_runtime.h>
#include <cuda_fp16.h>
#include <cstdint>
#include <math.h>

// Problem constants
#define BATCH 2
#define DMODEL 1024
#define SEQ 2048
#define HEADS 16
#define HDIM 64

// Scratch (allocation-free rule: __device__ globals)
__device__ float g_Q[BATCH * DMODEL * SEQ];
__device__ float g_K[BATCH * DMODEL * SEQ];
__device__ float g_V[BATCH * DMODEL * SEQ];
__device__ float g_X[BATCH * DMODEL * SEQ];

// ===========================================================================
// Helpers
// ===========================================================================
__device__ __forceinline__ uint32_t cvt_tf32(float v) {
    uint32_t r;
    asm("cvt.rna.tf32.f32 %0, %1;" : "=r"(r) : "f"(v));
    return r;
}

__device__ __forceinline__ uint32_t pack_h2(float lo, float hi) {
    __half2 h = __floats2half2_rn(lo, hi);
    return *reinterpret_cast<uint32_t*>(&h);
}

// D += A * B  (m16n8k8, tf32 inputs, fp32 accum). A row-major, B "col" (n x k).
__device__ __forceinline__ void mma_tf32(float d[4], const uint32_t a[4],
                                         uint32_t b0, uint32_t b1) {
    asm volatile(
        "mma.sync.aligned.m16n8k8.row.col.f32.tf32.tf32.f32 "
        "{%0,%1,%2,%3}, {%4,%5,%6,%7}, {%8,%9}, {%0,%1,%2,%3};\n"
        : "+f"(d[0]), "+f"(d[1]), "+f"(d[2]), "+f"(d[3])
        : "r"(a[0]), "r"(a[1]), "r"(a[2]), "r"(a[3]), "r"(b0), "r"(b1));
}

// D += A * B  (m16n8k16, fp16 inputs, fp32 accum). A row-major, B "col".
__device__ __forceinline__ void mma_f16(float d[4], const uint32_t a[4],
                                        uint32_t b0, uint32_t b1) {
    asm volatile(
        "mma.sync.aligned.m16n8k16.row.col.f32.f16.f16.f32 "
        "{%0,%1,%2,%3}, {%4,%5,%6,%7}, {%8,%9}, {%0,%1,%2,%3};\n"
        : "+f"(d[0]), "+f"(d[1]), "+f"(d[2]), "+f"(d[3])
        : "r"(a[0]), "r"(a[1]), "r"(a[2]), "r"(a[3]), "r"(b0), "r"(b1));
}

// ===========================================================================
// GEMM with bias (tensor-core tf32) — R8/R13 version verbatim (proven)
// ===========================================================================
#define APITCH 36
#define BPITCH 136

__global__ __launch_bounds__(256, 2) void gemm_mma(
    const float* __restrict__ A, const float* __restrict__ X,
    const float* __restrict__ bias, float* __restrict__ C)
{
    __shared__ uint32_t As[128 * APITCH];
    __shared__ uint32_t Bs[32 * BPITCH];

    const int tid = threadIdx.x;
    const int lane = tid & 31;
    const int wid = tid >> 5;
    const int wm = (wid >> 2) * 64;
    const int wn = (wid & 3) * 32;
    const int r = lane >> 2, c = lane & 3;
    const int b = blockIdx.z;
    const int row0 = blockIdx.y * 128, col0 = blockIdx.x * 128;
    const float* Xb = X + (size_t)b * DMODEL * SEQ;
    float* Cb = C + (size_t)b * DMODEL * SEQ;

    float acc[4][4][4];
#pragma unroll
    for (int mt = 0; mt < 4; mt++)
#pragma unroll
        for (int nt = 0; nt < 4; nt++)
#pragma unroll
            for (int i = 0; i < 4; i++) acc[mt][nt][i] = 0.f;

    for (int kt = 0; kt < DMODEL / 32; ++kt) {
        const int k0 = kt * 32;
        __syncthreads();
#pragma unroll
        for (int it = 0; it < 4; ++it) {
            int id = tid + it * 256;
            int m = id >> 3, k4 = (id & 7) << 2;
            float4 v = *(const float4*)(A + (size_t)(row0 + m) * DMODEL + k0 + k4);
            uint4 u = make_uint4(cvt_tf32(v.x), cvt_tf32(v.y),
                                 cvt_tf32(v.z), cvt_tf32(v.w));
            *(uint4*)&As[m * APITCH + k4] = u;
        }
#pragma unroll
        for (int it = 0; it < 4; ++it) {
            int id = tid + it * 256;
            int k = id >> 5, n4 = (id & 31) << 2;
            float4 v = *(const float4*)(Xb + (size_t)(k0 + k) * SEQ + col0 + n4);
            uint4 u = make_uint4(cvt_tf32(v.x), cvt_tf32(v.y),
                                 cvt_tf32(v.z), cvt_tf32(v.w));
            *(uint4*)&Bs[k * BPITCH + n4] = u;
        }
        __syncthreads();

#pragma unroll
        for (int ks = 0; ks < 4; ++ks) {
            uint32_t af[4][4], bf[4][2];
#pragma unroll
            for (int mt = 0; mt < 4; ++mt) {
                int mr = wm + mt * 16 + r;
                af[mt][0] = As[mr * APITCH + ks * 8 + c];
                af[mt][1] = As[(mr + 8) * APITCH + ks * 8 + c];
                af[mt][2] = As[mr * APITCH + ks * 8 + c + 4];
                af[mt][3] = As[(mr + 8) * APITCH + ks * 8 + c + 4];
            }
#pragma unroll
            for (int nt = 0; nt < 4; ++nt) {
                int nc = wn + nt * 8 + r;
                bf[nt][0] = Bs[(ks * 8 + c) * BPITCH + nc];
                bf[nt][1] = Bs[(ks * 8 + c + 4) * BPITCH + nc];
            }
#pragma unroll
            for (int mt = 0; mt < 4; ++mt)
#pragma unroll
                for (int nt = 0; nt < 4; ++nt)
                    mma_tf32(acc[mt][nt], af[mt], bf[nt][0], bf[nt][1]);
        }
    }

#pragma unroll
    for (int mt = 0; mt < 4; ++mt) {
        int r0 = row0 + wm + mt * 16 + r;
        float bv0 = __ldg(bias + r0);
        float bv1 = __ldg(bias + r0 + 8);
#pragma unroll
        for (int nt = 0; nt < 4; ++nt) {
            int c0 = col0 + wn + nt * 8 + c * 2;
            float2 v0 = make_float2(acc[mt][nt][0] + bv0, acc[mt][nt][1] + bv0);
            float2 v1 = make_float2(acc[mt][nt][2] + bv1, acc[mt][nt][3] + bv1);
            *(float2*)(Cb + (size_t)r0 * SEQ + c0) = v0;
            *(float2*)(Cb + (size_t)(r0 + 8) * SEQ + c0) = v1;
        }
    }
}

// ===========================================================================
// Flash attention v3: fp16 m16n8k16 MMAs. P stays in registers (C-fragment of
// S, packed to fp16x2, IS the A-fragment for the PV mma). Q/K/V staged in
// fp16x2 fragment-major chunks (128 words = 512B; lane l reads its uint4 at
// slot l^((l>>3)&3)).
//   Q (A-op, k=d):  chunk(wq, mt, kc): word(dp,q) = {Q[2dp][q], Q[2dp+1][q]}
//     offsets: lane = (q&7)*4 + (dp&3); word = ((q>>3)&1) + 2*((dp>>2)&1)
//   K (B-op, k=d):  chunk(tp, kc): word(dp,j) = {K[2dp][j], K[2dp+1][j]}
//     lane = (j&7)*4 + (dp&3); word = ((dp>>2)&1) + 2*((j>>3)&1)
//   V (B-op, k=j):  chunk(ntp, kc): word(d,jp) = {V[d][2jp], V[d][2jp+1]}
//     lane = (d&7)*4 + (jp&3); word = ((jp>>2)&1) + 2*((d>>3)&1)
// ===========================================================================
#define QF_OFF 0
#define KF_OFF 4096
#define VF_OFF 6144
#define ATTN_SMEM_B (8448 * 4)
#define XPITCH 132
#define QSCALE 0.1803368801111204f   // 0.125 * log2(e)

__global__ __launch_bounds__(128, 2) void attn_mma3(
    const float* __restrict__ Q, const float* __restrict__ K,
    const float* __restrict__ V, float* __restrict__ O)
{
    extern __shared__ uint32_t sm[];

    const int tid = threadIdx.x;
    const int lane = tid & 31, wid = tid >> 5;
    const int r = lane >> 2, c = lane & 3;
    const int lsw = lane ^ ((lane >> 3) & 3);

    const int bh = blockIdx.y;
    const int b = bh >> 4, h = bh & 15;
    const int n0 = blockIdx.x * 128;
    const size_t base = (size_t)b * DMODEL * SEQ + (size_t)h * SEQ;
    const size_t ds = (size_t)HEADS * SEQ;

    // ---------------- Stage Q (fp16x2 A-fragment-major, scaled) ------------
    {
        const int q_dp = tid >> 2;                  // d = 2*q_dp, 2*q_dp+1
        const int cQ = q_dp & 3, ahalf = (q_dp >> 2) & 1, kcQ = q_dp >> 3;
        const float* q0 = Q + base + (size_t)(2 * q_dp) * ds + n0;
        const float* q1 = q0 + ds;
#pragma unroll
        for (int it = 0; it < 8; ++it) {
            int qg = ((tid & 3) + it * 4) * 4;
            float4 va = *(const float4*)(q0 + qg);
            float4 vb = *(const float4*)(q1 + qg);
            float fa[4] = {va.x, va.y, va.z, va.w};
            float fb[4] = {vb.x, vb.y, vb.z, vb.w};
#pragma unroll
            for (int e = 0; e < 4; ++e) {
                int qloc = qg + e;
                int wq = qloc >> 5, mtq = (qloc >> 4) & 1;
                int rhq = (qloc >> 3) & 1, rQ = qloc & 7;
                int lq = rQ * 4 + cQ;
                int lsq = lq ^ ((lq >> 3) & 3);
                sm[QF_OFF + wq * 1024 + (mtq * 4 + kcQ) * 128 + lsq * 4
                   + rhq + 2 * ahalf] = pack_h2(fa[e] * QSCALE, fb[e] * QSCALE);
            }
        }
    }

    // K staging thread constants (paired-d loads)
    const int k_dp = tid >> 2;
    const int cK = k_dp & 3, kwh = (k_dp >> 2) & 1, kcK = k_dp >> 3;
    const float* kb0 = K + base + (size_t)(2 * k_dp) * ds;
    const float* kb1 = kb0 + ds;

    // V staging thread constants
    const int sd0 = tid >> 4;                 // d base; d = sd0 + 8*it
    const int sj0 = (tid & 15) * 4;           // j base
    const float* vbase = V + base + (size_t)sd0 * ds + sj0;
    const int jp0 = sj0 >> 1;                 // even
    const int kcV = jp0 >> 3, jplV = jp0 & 7;
    const int cV = jplV & 3, vwh = (jplV >> 2) & 1;
    const int lv0 = sd0 * 4 + cV;
    const int lsv0 = lv0 ^ ((lv0 >> 3) & 3);
    const int lv1 = sd0 * 4 + cV + 1;
    const int lsv1 = lv1 ^ ((lv1 >> 3) & 3);

    float m_[2][2] = {{-1e30f, -1e30f}, {-1e30f, -1e30f}};
    float l_[2][2] = {{0.f, 0.f}, {0.f, 0.f}};
    float acc[2][8][4];
#pragma unroll
    for (int mt = 0; mt < 2; ++mt)
#pragma unroll
        for (int nt = 0; nt < 8; ++nt)
#pragma unroll
            for (int i = 0; i < 4; ++i) acc[mt][nt][i] = 0.f;

    float4 kreg[8], vreg[8];

    // ---------------- Prologue: load + stage K(0), V(0) ----------------
#pragma unroll
    for (int it = 0; it < 4; ++it) {
        int jg = ((tid & 3) + it * 4) * 4;
        kreg[2 * it]     = *(const float4*)(kb0 + jg);
        kreg[2 * it + 1] = *(const float4*)(kb1 + jg);
    }
#pragma unroll
    for (int it = 0; it < 8; ++it)
        vreg[it] = *(const float4*)(vbase + (size_t)it * 8 * ds);

#pragma unroll
    for (int it = 0; it < 4; ++it) {
        int jg = ((tid & 3) + it * 4) * 4;
        float fa[4] = {kreg[2*it].x, kreg[2*it].y, kreg[2*it].z, kreg[2*it].w};
        float fb[4] = {kreg[2*it+1].x, kreg[2*it+1].y, kreg[2*it+1].z, kreg[2*it+1].w};
#pragma unroll
        for (int e = 0; e < 4; ++e) {
            int j = jg + e;
            int tp = j >> 4, hi = (j >> 3) & 1, rK = j & 7;
            int lk = rK * 4 + cK;
            int lsk = lk ^ ((lk >> 3) & 3);
            sm[KF_OFF + (tp * 4 + kcK) * 128 + lsk * 4 + kwh + 2 * hi]
                = pack_h2(fa[e], fb[e]);
        }
    }
#pragma unroll
    for (int it = 0; it < 8; ++it) {
        int ntpV = it >> 1, hiV = it & 1;
        int ba = VF_OFF + (ntpV * 4 + kcV) * 128;
        sm[ba + lsv0 * 4 + vwh + 2 * hiV] = pack_h2(vreg[it].x, vreg[it].y);
        sm[ba + lsv1 * 4 + vwh + 2 * hiV] = pack_h2(vreg[it].z, vreg[it].w);
    }
    __syncthreads();

    const int QW = QF_OFF + wid * 1024;

    // ---------------- Main loop over key tiles of 64 ----------------
    for (int t = 0; t < SEQ; t += 64) {
        const bool more = (t + 64) < SEQ;
        if (more) {
#pragma unroll
            for (int it = 0; it < 4; ++it) {
                int jg = ((tid & 3) + it * 4) * 4 + t + 64;
                kreg[2 * it]     = *(const float4*)(kb0 + jg);
                kreg[2 * it + 1] = *(const float4*)(kb1 + jg);
            }
        }

        // ---- S = Q K^T (fp16 k16) ----
        float s[2][8][4];
#pragma unroll
        for (int mt = 0; mt < 2; ++mt)
#pragma unroll
            for (int nt = 0; nt < 8; ++nt)
#pragma unroll
                for (int i = 0; i < 4; ++i) s[mt][nt][i] = 0.f;

#pragma unroll
        for (int kc = 0; kc < 4; ++kc) {
            uint4 qa0 = *(const uint4*)&sm[QW + kc * 128 + lsw * 4];
            uint4 qa1 = *(const uint4*)&sm[QW + (4 + kc) * 128 + lsw * 4];
            uint32_t a0[4] = {qa0.x, qa0.y, qa0.z, qa0.w};
            uint32_t a1[4] = {qa1.x, qa1.y, qa1.z, qa1.w};
#pragma unroll
            for (int tp = 0; tp < 4; ++tp) {
                uint4 kf = *(const uint4*)&sm[KF_OFF + (tp * 4 + kc) * 128 + lsw * 4];
                mma_f16(s[0][2 * tp], a0, kf.x, kf.y);
                mma_f16(s[0][2 * tp + 1], a0, kf.z, kf.w);
                mma_f16(s[1][2 * tp], a1, kf.x, kf.y);
                mma_f16(s[1][2 * tp + 1], a1, kf.z, kf.w);
            }
        }

        __syncthreads();   // all warps done reading Kf
        if (more) {
#pragma unroll
            for (int it = 0; it < 4; ++it) {
                int jg = ((tid & 3) + it * 4) * 4;
                float fa[4] = {kreg[2*it].x, kreg[2*it].y, kreg[2*it].z, kreg[2*it].w};
                float fb[4] = {kreg[2*it+1].x, kreg[2*it+1].y, kreg[2*it+1].z, kreg[2*it+1].w};
#pragma unroll
                for (int e = 0; e < 4; ++e) {
                    int j = jg + e;
                    int tp = j >> 4, hi = (j >> 3) & 1, rK = j & 7;
                    int lk = rK * 4 + cK;
                    int lsk = lk ^ ((lk >> 3) & 3);
                    sm[KF_OFF + (tp * 4 + kcK) * 128 + lsk * 4 + kwh + 2 * hi]
                        = pack_h2(fa[e], fb[e]);
                }
            }
#pragma unroll
            for (int it = 0; it < 8; ++it)
                vreg[it] = *(const float4*)(vbase + (size_t)it * 8 * ds + t + 64);
        }

        // ---- Online softmax (base-2 domain) ----
#pragma unroll
        for (int mt = 0; mt < 2; ++mt) {
#pragma unroll
            for (int hh = 0; hh < 2; ++hh) {
                float mx = -1e30f;
#pragma unroll
                for (int nt = 0; nt < 8; ++nt)
                    mx = fmaxf(mx, fmaxf(s[mt][nt][2 * hh], s[mt][nt][2 * hh + 1]));
                mx = fmaxf(mx, __shfl_xor_sync(0xffffffffu, mx, 1));
                mx = fmaxf(mx, __shfl_xor_sync(0xffffffffu, mx, 2));
                float mn = fmaxf(m_[mt][hh], mx);
                float sc = exp2f(m_[mt][hh] - mn);
                float sum = 0.f;
#pragma unroll
                for (int nt = 0; nt < 8; ++nt) {
                    float e0 = exp2f(s[mt][nt][2 * hh] - mn);
                    float e1 = exp2f(s[mt][nt][2 * hh + 1] - mn);
                    s[mt][nt][2 * hh] = e0;
                    s[mt][nt][2 * hh + 1] = e1;
                    sum += e0 + e1;
                }
                sum += __shfl_xor_sync(0xffffffffu, sum, 1);
                sum += __shfl_xor_sync(0xffffffffu, sum, 2);
                l_[mt][hh] = l_[mt][hh] * sc + sum;
                m_[mt][hh] = mn;
#pragma unroll
                for (int nt = 0; nt < 8; ++nt) {
                    acc[mt][nt][2 * hh] *= sc;
                    acc[mt][nt][2 * hh + 1] *= sc;
                }
            }
        }

        // ---- Pack P to fp16x2 A-fragments IN REGISTERS (no smem) ----
        uint32_t pa0[4][4], pa1[4][4];
#pragma unroll
        for (int kc = 0; kc < 4; ++kc) {
            pa0[kc][0] = pack_h2(s[0][2*kc][0],   s[0][2*kc][1]);
            pa0[kc][1] = pack_h2(s[0][2*kc][2],   s[0][2*kc][3]);
            pa0[kc][2] = pack_h2(s[0][2*kc+1][0], s[0][2*kc+1][1]);
            pa0[kc][3] = pack_h2(s[0][2*kc+1][2], s[0][2*kc+1][3]);
            pa1[kc][0] = pack_h2(s[1][2*kc][0],   s[1][2*kc][1]);
            pa1[kc][1] = pack_h2(s[1][2*kc][2],   s[1][2*kc][3]);
            pa1[kc][2] = pack_h2(s[1][2*kc+1][0], s[1][2*kc+1][1]);
            pa1[kc][3] = pack_h2(s[1][2*kc+1][2], s[1][2*kc+1][3]);
        }

        // ---- acc += P V ----
#pragma unroll
        for (int kc = 0; kc < 4; ++kc) {
#pragma unroll
            for (int ntp = 0; ntp < 4; ++ntp) {
                uint4 vf = *(const uint4*)&sm[VF_OFF + (ntp * 4 + kc) * 128 + lsw * 4];
                mma_f16(acc[0][2 * ntp], pa0[kc], vf.x, vf.y);
                mma_f16(acc[0][2 * ntp + 1], pa0[kc], vf.z, vf.w);
                mma_f16(acc[1][2 * ntp], pa1[kc], vf.x, vf.y);
                mma_f16(acc[1][2 * ntp + 1], pa1[kc], vf.z, vf.w);
            }
        }

        __syncthreads();   // all warps done reading Vf
        if (more) {
#pragma unroll
            for (int it = 0; it < 8; ++it) {
                int ntpV = it >> 1, hiV = it & 1;
                int ba = VF_OFF + (ntpV * 4 + kcV) * 128;
                sm[ba + lsv0 * 4 + vwh + 2 * hiV] = pack_h2(vreg[it].x, vreg[it].y);
                sm[ba + lsv1 * 4 + vwh + 2 * hiV] = pack_h2(vreg[it].z, vreg[it].w);
            }
        }
    }

    // ---------------- Epilogue: normalize, transpose, store ----------------
    __syncthreads();
    float* Xs = (float*)sm;   // [64 d][XPITCH]
#pragma unroll
    for (int mt = 0; mt < 2; ++mt) {
#pragma unroll
        for (int hh = 0; hh < 2; ++hh) {
            float inv = 1.f / l_[mt][hh];
            int q = wid * 32 + mt * 16 + r + 8 * hh;
#pragma unroll
            for (int nt = 0; nt < 8; ++nt) {
                int d0 = nt * 8 + 2 * c;
                Xs[d0 * XPITCH + q] = acc[mt][nt][2 * hh] * inv;
                Xs[(d0 + 1) * XPITCH + q] = acc[mt][nt][2 * hh + 1] * inv;
            }
        }
    }
    __syncthreads();
#pragma unroll
    for (int it = 0; it < 16; ++it) {
        int d = (tid >> 5) + it * 4;
        float4 v = *(const float4*)&Xs[d * XPITCH + lane * 4];
        *(float4*)(O + base + (size_t)d * ds + n0 + lane * 4) = v;
    }
}

// ---------------------------------------------------------------------------
// Launch.  metadata order: query, key, value, Wq, bq, Wk, bk, Wv, bv, Wm, bm
// ---------------------------------------------------------------------------
extern "C" void kernel_launch(void* const* d_in, const int* in_sizes, int n_in,
                              void* d_out, int out_size)
{
    const float* query = (const float*)d_in[0];
    const float* key   = (const float*)d_in[1];
    const float* value = (const float*)d_in[2];
    const float* Wq = (const float*)d_in[3];
    const float* bq = (const float*)d_in[4];
    const float* Wk = (const float*)d_in[5];
    const float* bk = (const float*)d_in[6];
    const float* Wv = (const float*)d_in[7];
    const float* bv = (const float*)d_in[8];
    const float* Wm = (const float*)d_in[9];
    const float* bm = (const float*)d_in[10];
    float* out = (float*)d_out;

    float *Qp, *Kp, *Vp, *Xp;
    cudaGetSymbolAddress((void**)&Qp, g_Q);
    cudaGetSymbolAddress((void**)&Kp, g_K);
    cudaGetSymbolAddress((void**)&Vp, g_V);
    cudaGetSymbolAddress((void**)&Xp, g_X);

    static cudaStream_t s1, s2;
    static cudaEvent_t evRoot, ev1, ev2;
    static bool init_done = false;
    if (!init_done) {
        cudaFuncSetAttribute(attn_mma3,
                             cudaFuncAttributeMaxDynamicSharedMemorySize,
                             ATTN_SMEM_B);
        cudaStreamCreateWithFlags(&s1, cudaStreamNonBlocking);
        cudaStreamCreateWithFlags(&s2, cudaStreamNonBlocking);
        cudaEventCreateWithFlags(&evRoot, cudaEventDisableTiming);
        cudaEventCreateWithFlags(&ev1, cudaEventDisableTiming);
        cudaEventCreateWithFlags(&ev2, cudaEventDisableTiming);
        init_done = true;
    }

    dim3 gGemm(SEQ / 128, DMODEL / 128, BATCH);  // (16, 8, 2)
    dim3 bGemm(256);

    // Fork: side streams join the capture via the root event.
    cudaEventRecord(evRoot, 0);
    cudaStreamWaitEvent(s1, evRoot, 0);
    cudaStreamWaitEvent(s2, evRoot, 0);

    gemm_mma<<<gGemm, bGemm, 0, 0>>>(Wq, query, bq, Qp);
    gemm_mma<<<gGemm, bGemm, 0, s1>>>(Wk, key,   bk, Kp);
    gemm_mma<<<gGemm, bGemm, 0, s2>>>(Wv, value, bv, Vp);

    // Join back onto the main stream.
    cudaEventRecord(ev1, s1);
    cudaEventRecord(ev2, s2);
    cudaStreamWaitEvent(0, ev1, 0);
    cudaStreamWaitEvent(0, ev2, 0);

    dim3 gAttn(SEQ / 128, BATCH * HEADS);  // (16, 32)
    attn_mma3<<<gAttn, 128, ATTN_SMEM_B>>>(Qp, Kp, Vp, Xp);

    gemm_mma<<<gGemm, bGemm>>>(Wm, Xp, bm, out);
}

// round 15
// speedup vs baseline: 2.1166x; 1.3474x over previous
#include <cuda_runtime.h>
#include <cuda_fp16.h>
#include <cstdint>
#include <math.h>

// Problem constants
#define BATCH 2
#define DMODEL 1024
#define SEQ 2048
#define HEADS 16
#define HDIM 64

// Scratch (allocation-free rule: __device__ globals)
__device__ float g_Q[BATCH * DMODEL * SEQ];
__device__ float g_K[BATCH * DMODEL * SEQ];
__device__ float g_V[BATCH * DMODEL * SEQ];
__device__ float g_X[BATCH * DMODEL * SEQ];

// ===========================================================================
// Helpers
// ===========================================================================
__device__ __forceinline__ uint32_t pack_h2(float lo, float hi) {
    __half2 h = __floats2half2_rn(lo, hi);
    return *reinterpret_cast<uint32_t*>(&h);
}

// D += A * B  (m16n8k16, fp16 inputs, fp32 accum). A row-major, B "col".
__device__ __forceinline__ void mma_f16(float d[4], const uint32_t a[4],
                                        uint32_t b0, uint32_t b1) {
    asm volatile(
        "mma.sync.aligned.m16n8k16.row.col.f32.f16.f16.f32 "
        "{%0,%1,%2,%3}, {%4,%5,%6,%7}, {%8,%9}, {%0,%1,%2,%3};\n"
        : "+f"(d[0]), "+f"(d[1]), "+f"(d[2]), "+f"(d[3])
        : "r"(a[0]), "r"(a[1]), "r"(a[2]), "r"(a[3]), "r"(b0), "r"(b1));
}

// ===========================================================================
// GEMM v4 (fp16 m16n8k16): C[b][m][n] = sum_k A[m][k] * X[b][k][n] + bias[m]
// Block 128x128, 8 warps (64x32 warp tiles), K staged in chunks of 64.
// smem words are half2 {v[2kp], v[2kp+1]} packed along k:
//   As[m][kp]  pitch 36  (128 m x 32 kp)  -> A fragments (kp = c / c+4)
//   Bs[kp][n]  pitch 136 (32 kp x 128 n)  -> B fragments
// Both fragment reads and scatter stores are (near-)conflict-free; the
// fragment<->layout maps are identical to the validated attn-v3 layouts.
// ===========================================================================
#define AP16 36
#define BP16 136

__global__ __launch_bounds__(256, 2) void gemm_mma_h(
    const float* __restrict__ A, const float* __restrict__ X,
    const float* __restrict__ bias, float* __restrict__ C)
{
    __shared__ uint32_t As[128 * AP16];
    __shared__ uint32_t Bs[32 * BP16];

    const int tid = threadIdx.x;
    const int lane = tid & 31;
    const int wid = tid >> 5;
    const int wm = (wid >> 2) * 64;
    const int wn = (wid & 3) * 32;
    const int r = lane >> 2, c = lane & 3;
    const int b = blockIdx.z;
    const int row0 = blockIdx.y * 128, col0 = blockIdx.x * 128;
    const float* Xb = X + (size_t)b * DMODEL * SEQ;
    float* Cb = C + (size_t)b * DMODEL * SEQ;

    float acc[4][4][4];
#pragma unroll
    for (int mt = 0; mt < 4; mt++)
#pragma unroll
        for (int nt = 0; nt < 4; nt++)
#pragma unroll
            for (int i = 0; i < 4; i++) acc[mt][nt][i] = 0.f;

    for (int kt = 0; kt < DMODEL / 64; ++kt) {
        const int k0 = kt * 64;
        __syncthreads();
        // ---- A tile: 128 m x 64 k -> As[m][32 kp] ----
#pragma unroll
        for (int it = 0; it < 8; ++it) {
            int id = tid + it * 256;              // 0..2047
            int m = id >> 4;
            int k4 = (id & 15) << 2;
            float4 v = *(const float4*)(A + (size_t)(row0 + m) * DMODEL + k0 + k4);
            int kp0 = (id & 15) << 1;
            As[m * AP16 + kp0]     = pack_h2(v.x, v.y);
            As[m * AP16 + kp0 + 1] = pack_h2(v.z, v.w);
        }
        // ---- B tile: 64 k x 128 n -> Bs[32 kp][128 n] ----
#pragma unroll
        for (int it = 0; it < 4; ++it) {
            int id = tid + it * 256;              // 0..1023
            int kp = id >> 5;
            int n4 = (id & 31) << 2;
            const float* x0 = Xb + (size_t)(k0 + 2 * kp) * SEQ + col0 + n4;
            float4 va = *(const float4*)x0;
            float4 vb = *(const float4*)(x0 + SEQ);
            Bs[kp * BP16 + n4 + 0] = pack_h2(va.x, vb.x);
            Bs[kp * BP16 + n4 + 1] = pack_h2(va.y, vb.y);
            Bs[kp * BP16 + n4 + 2] = pack_h2(va.z, vb.z);
            Bs[kp * BP16 + n4 + 3] = pack_h2(va.w, vb.w);
        }
        __syncthreads();

#pragma unroll
        for (int ks = 0; ks < 4; ++ks) {          // 4 k16 steps (8 kp each)
            uint32_t af[4][4], bf[4][2];
#pragma unroll
            for (int mt = 0; mt < 4; ++mt) {
                int mr = wm + mt * 16 + r;
                af[mt][0] = As[mr * AP16 + ks * 8 + c];
                af[mt][1] = As[(mr + 8) * AP16 + ks * 8 + c];
                af[mt][2] = As[mr * AP16 + ks * 8 + c + 4];
                af[mt][3] = As[(mr + 8) * AP16 + ks * 8 + c + 4];
            }
#pragma unroll
            for (int nt = 0; nt < 4; ++nt) {
                int nc = wn + nt * 8 + r;
                bf[nt][0] = Bs[(ks * 8 + c) * BP16 + nc];
                bf[nt][1] = Bs[(ks * 8 + c + 4) * BP16 + nc];
            }
#pragma unroll
            for (int mt = 0; mt < 4; ++mt)
#pragma unroll
                for (int nt = 0; nt < 4; ++nt)
                    mma_f16(acc[mt][nt], af[mt], bf[nt][0], bf[nt][1]);
        }
    }

    // Epilogue: fused bias, direct float2 stores
#pragma unroll
    for (int mt = 0; mt < 4; ++mt) {
        int r0 = row0 + wm + mt * 16 + r;
        float bv0 = __ldg(bias + r0);
        float bv1 = __ldg(bias + r0 + 8);
#pragma unroll
        for (int nt = 0; nt < 4; ++nt) {
            int c0 = col0 + wn + nt * 8 + c * 2;
            float2 v0 = make_float2(acc[mt][nt][0] + bv0, acc[mt][nt][1] + bv0);
            float2 v1 = make_float2(acc[mt][nt][2] + bv1, acc[mt][nt][3] + bv1);
            *(float2*)(Cb + (size_t)r0 * SEQ + c0) = v0;
            *(float2*)(Cb + (size_t)(r0 + 8) * SEQ + c0) = v1;
        }
    }
}

// ===========================================================================
// Flash attention v3 (verbatim from R14): fp16 m16n8k16, register-resident P.
// ===========================================================================
#define QF_OFF 0
#define KF_OFF 4096
#define VF_OFF 6144
#define ATTN_SMEM_B (8448 * 4)
#define XPITCH 132
#define QSCALE 0.1803368801111204f   // 0.125 * log2(e)

__global__ __launch_bounds__(128, 2) void attn_mma3(
    const float* __restrict__ Q, const float* __restrict__ K,
    const float* __restrict__ V, float* __restrict__ O)
{
    extern __shared__ uint32_t sm[];

    const int tid = threadIdx.x;
    const int lane = tid & 31, wid = tid >> 5;
    const int r = lane >> 2, c = lane & 3;
    const int lsw = lane ^ ((lane >> 3) & 3);

    const int bh = blockIdx.y;
    const int b = bh >> 4, h = bh & 15;
    const int n0 = blockIdx.x * 128;
    const size_t base = (size_t)b * DMODEL * SEQ + (size_t)h * SEQ;
    const size_t ds = (size_t)HEADS * SEQ;

    // ---------------- Stage Q (fp16x2 A-fragment-major, scaled) ------------
    {
        const int q_dp = tid >> 2;
        const int cQ = q_dp & 3, ahalf = (q_dp >> 2) & 1, kcQ = q_dp >> 3;
        const float* q0 = Q + base + (size_t)(2 * q_dp) * ds + n0;
        const float* q1 = q0 + ds;
#pragma unroll
        for (int it = 0; it < 8; ++it) {
            int qg = ((tid & 3) + it * 4) * 4;
            float4 va = *(const float4*)(q0 + qg);
            float4 vb = *(const float4*)(q1 + qg);
            float fa[4] = {va.x, va.y, va.z, va.w};
            float fb[4] = {vb.x, vb.y, vb.z, vb.w};
#pragma unroll
            for (int e = 0; e < 4; ++e) {
                int qloc = qg + e;
                int wq = qloc >> 5, mtq = (qloc >> 4) & 1;
                int rhq = (qloc >> 3) & 1, rQ = qloc & 7;
                int lq = rQ * 4 + cQ;
                int lsq = lq ^ ((lq >> 3) & 3);
                sm[QF_OFF + wq * 1024 + (mtq * 4 + kcQ) * 128 + lsq * 4
                   + rhq + 2 * ahalf] = pack_h2(fa[e] * QSCALE, fb[e] * QSCALE);
            }
        }
    }

    const int k_dp = tid >> 2;
    const int cK = k_dp & 3, kwh = (k_dp >> 2) & 1, kcK = k_dp >> 3;
    const float* kb0 = K + base + (size_t)(2 * k_dp) * ds;
    const float* kb1 = kb0 + ds;

    const int sd0 = tid >> 4;
    const int sj0 = (tid & 15) * 4;
    const float* vbase = V + base + (size_t)sd0 * ds + sj0;
    const int jp0 = sj0 >> 1;
    const int kcV = jp0 >> 3, jplV = jp0 & 7;
    const int cV = jplV & 3, vwh = (jplV >> 2) & 1;
    const int lv0 = sd0 * 4 + cV;
    const int lsv0 = lv0 ^ ((lv0 >> 3) & 3);
    const int lv1 = sd0 * 4 + cV + 1;
    const int lsv1 = lv1 ^ ((lv1 >> 3) & 3);

    float m_[2][2] = {{-1e30f, -1e30f}, {-1e30f, -1e30f}};
    float l_[2][2] = {{0.f, 0.f}, {0.f, 0.f}};
    float acc[2][8][4];
#pragma unroll
    for (int mt = 0; mt < 2; ++mt)
#pragma unroll
        for (int nt = 0; nt < 8; ++nt)
#pragma unroll
            for (int i = 0; i < 4; ++i) acc[mt][nt][i] = 0.f;

    float4 kreg[8], vreg[8];

#pragma unroll
    for (int it = 0; it < 4; ++it) {
        int jg = ((tid & 3) + it * 4) * 4;
        kreg[2 * it]     = *(const float4*)(kb0 + jg);
        kreg[2 * it + 1] = *(const float4*)(kb1 + jg);
    }
#pragma unroll
    for (int it = 0; it < 8; ++it)
        vreg[it] = *(const float4*)(vbase + (size_t)it * 8 * ds);

#pragma unroll
    for (int it = 0; it < 4; ++it) {
        int jg = ((tid & 3) + it * 4) * 4;
        float fa[4] = {kreg[2*it].x, kreg[2*it].y, kreg[2*it].z, kreg[2*it].w};
        float fb[4] = {kreg[2*it+1].x, kreg[2*it+1].y, kreg[2*it+1].z, kreg[2*it+1].w};
#pragma unroll
        for (int e = 0; e < 4; ++e) {
            int j = jg + e;
            int tp = j >> 4, hi = (j >> 3) & 1, rK = j & 7;
            int lk = rK * 4 + cK;
            int lsk = lk ^ ((lk >> 3) & 3);
            sm[KF_OFF + (tp * 4 + kcK) * 128 + lsk * 4 + kwh + 2 * hi]
                = pack_h2(fa[e], fb[e]);
        }
    }
#pragma unroll
    for (int it = 0; it < 8; ++it) {
        int ntpV = it >> 1, hiV = it & 1;
        int ba = VF_OFF + (ntpV * 4 + kcV) * 128;
        sm[ba + lsv0 * 4 + vwh + 2 * hiV] = pack_h2(vreg[it].x, vreg[it].y);
        sm[ba + lsv1 * 4 + vwh + 2 * hiV] = pack_h2(vreg[it].z, vreg[it].w);
    }
    __syncthreads();

    const int QW = QF_OFF + wid * 1024;

    for (int t = 0; t < SEQ; t += 64) {
        const bool more = (t + 64) < SEQ;
        if (more) {
#pragma unroll
            for (int it = 0; it < 4; ++it) {
                int jg = ((tid & 3) + it * 4) * 4 + t + 64;
                kreg[2 * it]     = *(const float4*)(kb0 + jg);
                kreg[2 * it + 1] = *(const float4*)(kb1 + jg);
            }
        }

        float s[2][8][4];
#pragma unroll
        for (int mt = 0; mt < 2; ++mt)
#pragma unroll
            for (int nt = 0; nt < 8; ++nt)
#pragma unroll
                for (int i = 0; i < 4; ++i) s[mt][nt][i] = 0.f;

#pragma unroll
        for (int kc = 0; kc < 4; ++kc) {
            uint4 qa0 = *(const uint4*)&sm[QW + kc * 128 + lsw * 4];
            uint4 qa1 = *(const uint4*)&sm[QW + (4 + kc) * 128 + lsw * 4];
            uint32_t a0[4] = {qa0.x, qa0.y, qa0.z, qa0.w};
            uint32_t a1[4] = {qa1.x, qa1.y, qa1.z, qa1.w};
#pragma unroll
            for (int tp = 0; tp < 4; ++tp) {
                uint4 kf = *(const uint4*)&sm[KF_OFF + (tp * 4 + kc) * 128 + lsw * 4];
                mma_f16(s[0][2 * tp], a0, kf.x, kf.y);
                mma_f16(s[0][2 * tp + 1], a0, kf.z, kf.w);
                mma_f16(s[1][2 * tp], a1, kf.x, kf.y);
                mma_f16(s[1][2 * tp + 1], a1, kf.z, kf.w);
            }
        }

        __syncthreads();
        if (more) {
#pragma unroll
            for (int it = 0; it < 4; ++it) {
                int jg = ((tid & 3) + it * 4) * 4;
                float fa[4] = {kreg[2*it].x, kreg[2*it].y, kreg[2*it].z, kreg[2*it].w};
                float fb[4] = {kreg[2*it+1].x, kreg[2*it+1].y, kreg[2*it+1].z, kreg[2*it+1].w};
#pragma unroll
                for (int e = 0; e < 4; ++e) {
                    int j = jg + e;
                    int tp = j >> 4, hi = (j >> 3) & 1, rK = j & 7;
                    int lk = rK * 4 + cK;
                    int lsk = lk ^ ((lk >> 3) & 3);
                    sm[KF_OFF + (tp * 4 + kcK) * 128 + lsk * 4 + kwh + 2 * hi]
                        = pack_h2(fa[e], fb[e]);
                }
            }
#pragma unroll
            for (int it = 0; it < 8; ++it)
                vreg[it] = *(const float4*)(vbase + (size_t)it * 8 * ds + t + 64);
        }

#pragma unroll
        for (int mt = 0; mt < 2; ++mt) {
#pragma unroll
            for (int hh = 0; hh < 2; ++hh) {
                float mx = -1e30f;
#pragma unroll
                for (int nt = 0; nt < 8; ++nt)
                    mx = fmaxf(mx, fmaxf(s[mt][nt][2 * hh], s[mt][nt][2 * hh + 1]));
                mx = fmaxf(mx, __shfl_xor_sync(0xffffffffu, mx, 1));
                mx = fmaxf(mx, __shfl_xor_sync(0xffffffffu, mx, 2));
                float mn = fmaxf(m_[mt][hh], mx);
                float sc = exp2f(m_[mt][hh] - mn);
                float sum = 0.f;
#pragma unroll
                for (int nt = 0; nt < 8; ++nt) {
                    float e0 = exp2f(s[mt][nt][2 * hh] - mn);
                    float e1 = exp2f(s[mt][nt][2 * hh + 1] - mn);
                    s[mt][nt][2 * hh] = e0;
                    s[mt][nt][2 * hh + 1] = e1;
                    sum += e0 + e1;
                }
                sum += __shfl_xor_sync(0xffffffffu, sum, 1);
                sum += __shfl_xor_sync(0xffffffffu, sum, 2);
                l_[mt][hh] = l_[mt][hh] * sc + sum;
                m_[mt][hh] = mn;
#pragma unroll
                for (int nt = 0; nt < 8; ++nt) {
                    acc[mt][nt][2 * hh] *= sc;
                    acc[mt][nt][2 * hh + 1] *= sc;
                }
            }
        }

        uint32_t pa0[4][4], pa1[4][4];
#pragma unroll
        for (int kc = 0; kc < 4; ++kc) {
            pa0[kc][0] = pack_h2(s[0][2*kc][0],   s[0][2*kc][1]);
            pa0[kc][1] = pack_h2(s[0][2*kc][2],   s[0][2*kc][3]);
            pa0[kc][2] = pack_h2(s[0][2*kc+1][0], s[0][2*kc+1][1]);
            pa0[kc][3] = pack_h2(s[0][2*kc+1][2], s[0][2*kc+1][3]);
            pa1[kc][0] = pack_h2(s[1][2*kc][0],   s[1][2*kc][1]);
            pa1[kc][1] = pack_h2(s[1][2*kc][2],   s[1][2*kc][3]);
            pa1[kc][2] = pack_h2(s[1][2*kc+1][0], s[1][2*kc+1][1]);
            pa1[kc][3] = pack_h2(s[1][2*kc+1][2], s[1][2*kc+1][3]);
        }

#pragma unroll
        for (int kc = 0; kc < 4; ++kc) {
#pragma unroll
            for (int ntp = 0; ntp < 4; ++ntp) {
                uint4 vf = *(const uint4*)&sm[VF_OFF + (ntp * 4 + kc) * 128 + lsw * 4];
                mma_f16(acc[0][2 * ntp], pa0[kc], vf.x, vf.y);
                mma_f16(acc[0][2 * ntp + 1], pa0[kc], vf.z, vf.w);
                mma_f16(acc[1][2 * ntp], pa1[kc], vf.x, vf.y);
                mma_f16(acc[1][2 * ntp + 1], pa1[kc], vf.z, vf.w);
            }
        }

        __syncthreads();
        if (more) {
#pragma unroll
            for (int it = 0; it < 8; ++it) {
                int ntpV = it >> 1, hiV = it & 1;
                int ba = VF_OFF + (ntpV * 4 + kcV) * 128;
                sm[ba + lsv0 * 4 + vwh + 2 * hiV] = pack_h2(vreg[it].x, vreg[it].y);
                sm[ba + lsv1 * 4 + vwh + 2 * hiV] = pack_h2(vreg[it].z, vreg[it].w);
            }
        }
    }

    __syncthreads();
    float* Xs = (float*)sm;
#pragma unroll
    for (int mt = 0; mt < 2; ++mt) {
#pragma unroll
        for (int hh = 0; hh < 2; ++hh) {
            float inv = 1.f / l_[mt][hh];
            int q = wid * 32 + mt * 16 + r + 8 * hh;
#pragma unroll
            for (int nt = 0; nt < 8; ++nt) {
                int d0 = nt * 8 + 2 * c;
                Xs[d0 * XPITCH + q] = acc[mt][nt][2 * hh] * inv;
                Xs[(d0 + 1) * XPITCH + q] = acc[mt][nt][2 * hh + 1] * inv;
            }
        }
    }
    __syncthreads();
#pragma unroll
    for (int it = 0; it < 16; ++it) {
        int d = (tid >> 5) + it * 4;
        float4 v = *(const float4*)&Xs[d * XPITCH + lane * 4];
        *(float4*)(O + base + (size_t)d * ds + n0 + lane * 4) = v;
    }
}

// ---------------------------------------------------------------------------
// Launch.  metadata order: query, key, value, Wq, bq, Wk, bk, Wv, bv, Wm, bm
// ---------------------------------------------------------------------------
extern "C" void kernel_launch(void* const* d_in, const int* in_sizes, int n_in,
                              void* d_out, int out_size)
{
    const float* query = (const float*)d_in[0];
    const float* key   = (const float*)d_in[1];
    const float* value = (const float*)d_in[2];
    const float* Wq = (const float*)d_in[3];
    const float* bq = (const float*)d_in[4];
    const float* Wk = (const float*)d_in[5];
    const float* bk = (const float*)d_in[6];
    const float* Wv = (const float*)d_in[7];
    const float* bv = (const float*)d_in[8];
    const float* Wm = (const float*)d_in[9];
    const float* bm = (const float*)d_in[10];
    float* out = (float*)d_out;

    float *Qp, *Kp, *Vp, *Xp;
    cudaGetSymbolAddress((void**)&Qp, g_Q);
    cudaGetSymbolAddress((void**)&Kp, g_K);
    cudaGetSymbolAddress((void**)&Vp, g_V);
    cudaGetSymbolAddress((void**)&Xp, g_X);

    static cudaStream_t s1, s2;
    static cudaEvent_t evRoot, ev1, ev2;
    static bool init_done = false;
    if (!init_done) {
        cudaFuncSetAttribute(attn_mma3,
                             cudaFuncAttributeMaxDynamicSharedMemorySize,
                             ATTN_SMEM_B);
        cudaStreamCreateWithFlags(&s1, cudaStreamNonBlocking);
        cudaStreamCreateWithFlags(&s2, cudaStreamNonBlocking);
        cudaEventCreateWithFlags(&evRoot, cudaEventDisableTiming);
        cudaEventCreateWithFlags(&ev1, cudaEventDisableTiming);
        cudaEventCreateWithFlags(&ev2, cudaEventDisableTiming);
        init_done = true;
    }

    dim3 gGemm(SEQ / 128, DMODEL / 128, BATCH);  // (16, 8, 2)
    dim3 bGemm(256);

    // Fork: side streams join the capture via the root event.
    cudaEventRecord(evRoot, 0);
    cudaStreamWaitEvent(s1, evRoot, 0);
    cudaStreamWaitEvent(s2, evRoot, 0);

    gemm_mma_h<<<gGemm, bGemm, 0, 0>>>(Wq, query, bq, Qp);
    gemm_mma_h<<<gGemm, bGemm, 0, s1>>>(Wk, key,   bk, Kp);
    gemm_mma_h<<<gGemm, bGemm, 0, s2>>>(Wv, value, bv, Vp);

    // Join back onto the main stream.
    cudaEventRecord(ev1, s1);
    cudaEventRecord(ev2, s2);
    cudaStreamWaitEvent(0, ev1, 0);
    cudaStreamWaitEvent(0, ev2, 0);

    dim3 gAttn(SEQ / 128, BATCH * HEADS);  // (16, 32)
    attn_mma3<<<gAttn, 128, ATTN_SMEM_B>>>(Qp, Kp, Vp, Xp);

    gemm_mma_h<<<gGemm, bGemm>>>(Wm, Xp, bm, out);
}